// round 14
// baseline (speedup 1.0000x reference)
#include <cuda_runtime.h>
#include <cuda_bf16.h>
#include <cstdint>

#define N_NODES 50000
#define N_EDGES 800000
#define F_IN    256
#define NH      4
#define HD      64
#define SLOT_W  64

// ---------------- scratch (device globals; no allocs allowed) ----------------
__device__ float          g_hsrc[N_NODES * HD];
__device__ float          g_hdst[N_NODES * HD];
__device__ int            g_deg[N_NODES];             // starts 0; agg re-zeroes after use
__device__ int            g_slots[N_NODES * SLOT_W];  // padded CSR payload: src ids
__device__ __nv_bfloat16  g_whi[128 * F_IN];          // Wcat bf16 hi
__device__ __nv_bfloat16  g_wlo[128 * F_IN];          // Wcat bf16 residual

// ---------------- W prep: fp32 -> bf16 hi/lo, once per launch ----------------
__global__ void wprep_kernel(const float* __restrict__ Wsrc,
                             const float* __restrict__ Wdst) {
    int i = blockIdx.x * blockDim.x + threadIdx.x;   // over 128*256
    if (i >= 128 * F_IN) return;
    int row = i >> 8, col = i & 255;
    float v = (row < 64) ? Wsrc[row * F_IN + col] : Wdst[(row - 64) * F_IN + col];
    __nv_bfloat16 h = __float2bfloat16_rn(v);
    g_whi[i] = h;
    g_wlo[i] = __float2bfloat16_rn(v - __bfloat162float(h));
}

// ---------------- padded-CSR scatter (single kernel, no init/scan) ----------------
__global__ void scatter_kernel(const int* __restrict__ src, const int* __restrict__ dst) {
    int base = (blockIdx.x * blockDim.x + threadIdx.x) * 4;
    if (base + 3 < N_EDGES) {
        int4 d = *(const int4*)(dst + base);
        int4 s = *(const int4*)(src + base);
        int p0 = atomicAdd(&g_deg[d.x], 1);
        int p1 = atomicAdd(&g_deg[d.y], 1);
        int p2 = atomicAdd(&g_deg[d.z], 1);
        int p3 = atomicAdd(&g_deg[d.w], 1);
        g_slots[d.x * SLOT_W + p0] = s.x;
        g_slots[d.y * SLOT_W + p1] = s.y;
        g_slots[d.z * SLOT_W + p2] = s.z;
        g_slots[d.w * SLOT_W + p3] = s.w;
    } else {
        for (int e = base; e < N_EDGES; e++) {
            int p = atomicAdd(&g_deg[dst[e]], 1);
            g_slots[dst[e] * SLOT_W + p] = src[e];
        }
    }
}

// ---------------- helpers ----------------
__device__ __forceinline__ uint32_t smem_u32(const void* p) {
    uint32_t a;
    asm("{ .reg .u64 t; cvta.to.shared.u64 t, %1; cvt.u32.u64 %0, t; }" : "=r"(a) : "l"(p));
    return a;
}
__device__ __forceinline__ void ldsm4(unsigned r[4], uint32_t a) {
    asm volatile("ldmatrix.sync.aligned.m8n8.x4.shared.b16 {%0,%1,%2,%3}, [%4];"
                 : "=r"(r[0]), "=r"(r[1]), "=r"(r[2]), "=r"(r[3]) : "r"(a));
}
__device__ __forceinline__ void mma_bf16(float c[4], const unsigned a[4], const unsigned b[2]) {
    asm volatile(
        "mma.sync.aligned.m16n8k16.row.col.f32.bf16.bf16.f32 "
        "{%0,%1,%2,%3}, {%4,%5,%6,%7}, {%8,%9}, {%0,%1,%2,%3};"
        : "+f"(c[0]), "+f"(c[1]), "+f"(c[2]), "+f"(c[3])
        : "r"(a[0]), "r"(a[1]), "r"(a[2]), "r"(a[3]), "r"(b[0]), "r"(b[1]));
}
__device__ __forceinline__ void cvt8(float4 a, float4 b, uint4& hi, uint4& lo) {
    float xs[8] = {a.x, a.y, a.z, a.w, b.x, b.y, b.z, b.w};
    unsigned h[4], l[4];
    #pragma unroll
    for (int i = 0; i < 4; i++) {
        float x = xs[2 * i], y = xs[2 * i + 1];
        __nv_bfloat16 hx = __float2bfloat16_rn(x);
        __nv_bfloat16 hy = __float2bfloat16_rn(y);
        __nv_bfloat16 lx = __float2bfloat16_rn(x - __bfloat162float(hx));
        __nv_bfloat16 ly = __float2bfloat16_rn(y - __bfloat162float(hy));
        unsigned short uhx = *(unsigned short*)&hx, uhy = *(unsigned short*)&hy;
        unsigned short ulx = *(unsigned short*)&lx, uly = *(unsigned short*)&ly;
        h[i] = (unsigned)uhx | ((unsigned)uhy << 16);
        l[i] = (unsigned)ulx | ((unsigned)uly << 16);
    }
    hi = make_uint4(h[0], h[1], h[2], h[3]);
    lo = make_uint4(l[0], l[1], l[2], l[3]);
}

// ---------------- HMMA bf16-split projection GEMM v2.1 ----------------
// Same as round-9 proven v2, but B loads pre-converted bf16 (g_whi/g_wlo):
// half the B LDG bytes, zero B-side cvt in the hot loop.
#define RSB2   80
#define TILE2  10240
#define STG2   40960
#define SM_TOT 81920

__global__ __launch_bounds__(256, 2)
void proj_mma_kernel(const float* __restrict__ feat,
                     const float* __restrict__ bsrc, const float* __restrict__ bdst)
{
    extern __shared__ char smem[];
    const uint32_t sb = smem_u32(smem);
    const int tid  = threadIdx.x;
    const int wid  = tid >> 5, lane = tid & 31;
    const int warp_m = wid & 3;
    const int warp_n = wid >> 2;
    const int m0 = blockIdx.x * 128;

    float acc[2][8][4];
    #pragma unroll
    for (int mt = 0; mt < 2; mt++)
        #pragma unroll
        for (int nt = 0; nt < 8; nt++)
            #pragma unroll
            for (int j = 0; j < 4; j++) acc[mt][nt][j] = 0.0f;

    float4 pa[2][2];
    uint4  pbh[2], pbl[2];

    #define LOAD_AB(c) do {                                                       \
        _Pragma("unroll")                                                         \
        for (int i = 0; i < 2; i++) {                                             \
            int t = tid + i * 256, row = t >> 2, seg = t & 3;                     \
            int node = m0 + row; if (node >= N_NODES) node = N_NODES - 1;         \
            const float* p = feat + (size_t)node * F_IN + (c) * 32 + seg * 8;     \
            pa[i][0] = *(const float4*)p; pa[i][1] = *(const float4*)(p + 4);     \
            int wcol = (c) * 32 + seg * 8;                                        \
            pbh[i] = *(const uint4*)(g_whi + row * F_IN + wcol);                  \
            pbl[i] = *(const uint4*)(g_wlo + row * F_IN + wcol);                  \
        } } while (0)

    #define STORE_AB(st) do {                                                     \
        _Pragma("unroll")                                                         \
        for (int i = 0; i < 2; i++) {                                             \
            int t = tid + i * 256, row = t >> 2, seg = t & 3;                     \
            uint32_t off = (uint32_t)((st) * STG2 + row * RSB2 + seg * 16);       \
            uint4 hi, lo;                                                         \
            cvt8(pa[i][0], pa[i][1], hi, lo);                                     \
            *(uint4*)(smem + off)             = hi;                               \
            *(uint4*)(smem + TILE2 + off)     = lo;                               \
            *(uint4*)(smem + 2 * TILE2 + off) = pbh[i];                           \
            *(uint4*)(smem + 3 * TILE2 + off) = pbl[i];                           \
        } } while (0)

    LOAD_AB(0);
    STORE_AB(0);
    __syncthreads();

    const uint32_t a_off = (uint32_t)((warp_m * 32 + (lane & 15)) * RSB2 + (lane >> 4) * 16);
    const uint32_t b_off = (uint32_t)((warp_n * 64 + (lane & 7) + ((lane >> 4) & 1) * 8) * RSB2 +
                                      ((lane >> 3) & 1) * 16);

    for (int c = 0; c < 8; c++) {
        const uint32_t st = (uint32_t)(c & 1) * STG2;
        if (c < 7) LOAD_AB(c + 1);

        #pragma unroll
        for (int ks = 0; ks < 2; ks++) {
            unsigned ah[2][4], al[2][4];
            #pragma unroll
            for (int mt = 0; mt < 2; mt++) {
                ldsm4(ah[mt], sb + st + a_off + (uint32_t)(mt * 16 * RSB2 + ks * 32));
                ldsm4(al[mt], sb + st + TILE2 + a_off + (uint32_t)(mt * 16 * RSB2 + ks * 32));
            }
            unsigned bh[4][4], bl[4][4];
            #pragma unroll
            for (int p = 0; p < 4; p++) {
                ldsm4(bh[p], sb + st + 2 * TILE2 + b_off + (uint32_t)(p * 16 * RSB2 + ks * 32));
                ldsm4(bl[p], sb + st + 3 * TILE2 + b_off + (uint32_t)(p * 16 * RSB2 + ks * 32));
            }
            #pragma unroll
            for (int mt = 0; mt < 2; mt++)
                #pragma unroll
                for (int nt = 0; nt < 8; nt++) {
                    const unsigned* bhf = &bh[nt >> 1][(nt & 1) * 2];
                    const unsigned* blf = &bl[nt >> 1][(nt & 1) * 2];
                    mma_bf16(acc[mt][nt], ah[mt], bhf);
                    mma_bf16(acc[mt][nt], ah[mt], blf);
                    mma_bf16(acc[mt][nt], al[mt], bhf);
                }
        }
        if (c < 7) STORE_AB((c + 1) & 1);
        __syncthreads();
    }

    #pragma unroll
    for (int mt = 0; mt < 2; mt++)
        #pragma unroll
        for (int nt = 0; nt < 8; nt++) {
            int row = warp_m * 32 + mt * 16 + (lane >> 2);
            int o   = warp_n * 64 + nt * 8 + (lane & 3) * 2;
            float* buf; int col;
            float b0, b1;
            if (o < 64) { col = o;      buf = g_hsrc; b0 = bsrc[col]; b1 = bsrc[col + 1]; }
            else        { col = o - 64; buf = g_hdst; b0 = bdst[col]; b1 = bdst[col + 1]; }
            int n0 = m0 + row, n1 = m0 + row + 8;
            if (n0 < N_NODES)
                *(float2*)(buf + (size_t)n0 * HD + col) =
                    make_float2(acc[mt][nt][0] + b0, acc[mt][nt][1] + b1);
            if (n1 < N_NODES)
                *(float2*)(buf + (size_t)n1 * HD + col) =
                    make_float2(acc[mt][nt][2] + b0, acc[mt][nt][3] + b1);
        }
}

// ---------------- separator (keeps agg 4th in submission order for ncu) ----------------
__global__ void sep_kernel() {}

// ---------------- aggregation (round-12 proven config) ----------------
__global__ __launch_bounds__(256) void agg_kernel(float* __restrict__ out,
                                                  const float* __restrict__ attn)
{
    int warp = (blockIdx.x * blockDim.x + threadIdx.x) >> 5;
    int lane = threadIdx.x & 31;
    if (warp >= N_NODES) return;
    const int d    = warp;
    const int half = lane >> 4;
    const int l16  = lane & 15;

    float4 er = ((const float4*)(g_hdst + (size_t)d * HD))[l16];
    float4 aw = ((const float4*)attn)[l16];

    const int cnt   = g_deg[d];
    const int start = d * SLOT_W;

    float4 acc = make_float4(0.f, 0.f, 0.f, 0.f);
    float  s   = 0.f;

    for (int base = 0; base < cnt; base += 32) {
        int m = cnt - base; if (m > 32) m = 32;
        int sn_l = (lane < m) ? g_slots[start + base + lane] : 0;

        #pragma unroll 2
        for (int i = 0; i < m; i += 2) {
            int   eidx  = i + half;
            float valid = (eidx < m) ? 1.0f : 0.0f;
            int   sn    = __shfl_sync(0xFFFFFFFFu, sn_l, eidx & 31);
            float4 el = ((const float4*)(g_hsrc + (size_t)sn * HD))[l16];
            float vx = el.x + er.x, vy = el.y + er.y,
                  vz = el.z + er.z, vw = el.w + er.w;
            vx = fmaxf(vx, 0.f) + 0.2f * fminf(vx, 0.f);
            vy = fmaxf(vy, 0.f) + 0.2f * fminf(vy, 0.f);
            vz = fmaxf(vz, 0.f) + 0.2f * fminf(vz, 0.f);
            vw = fmaxf(vw, 0.f) + 0.2f * fminf(vw, 0.f);
            float p = vx * aw.x + vy * aw.y + vz * aw.z + vw * aw.w;
            p += __shfl_xor_sync(0xFFFFFFFFu, p, 1);
            p += __shfl_xor_sync(0xFFFFFFFFu, p, 2);
            float a = __expf(p) * valid;
            acc.x += a * el.x;
            acc.y += a * el.y;
            acc.z += a * el.z;
            acc.w += a * el.w;
            s     += a;
        }
    }

    acc.x += __shfl_xor_sync(0xFFFFFFFFu, acc.x, 16);
    acc.y += __shfl_xor_sync(0xFFFFFFFFu, acc.y, 16);
    acc.z += __shfl_xor_sync(0xFFFFFFFFu, acc.z, 16);
    acc.w += __shfl_xor_sync(0xFFFFFFFFu, acc.w, 16);
    s     += __shfl_xor_sync(0xFFFFFFFFu, s, 16);

    if (lane == 0) g_deg[d] = 0;   // restore invariant for next graph replay

    if (half == 0) {
        float inv = (s > 0.f) ? (1.f / s) : 0.f;
        ((float4*)(out + (size_t)d * HD))[l16] =
            make_float4(acc.x * inv, acc.y * inv, acc.z * inv, acc.w * inv);
    }
}

extern "C" void kernel_launch(void* const* d_in, const int* in_sizes, int n_in,
                              void* d_out, int out_size)
{
    const float* feat = (const float*)d_in[0];
    const int*   src  = (const int*)d_in[1];
    const int*   dst  = (const int*)d_in[2];
    const float* Wsrc = (const float*)d_in[3];
    const float* bsrc = (const float*)d_in[4];
    const float* Wdst = (const float*)d_in[5];
    const float* bdst = (const float*)d_in[6];
    const float* attn = (const float*)d_in[7];
    float* out = (float*)d_out;

    cudaFuncSetAttribute(proj_mma_kernel, cudaFuncAttributeMaxDynamicSharedMemorySize, SM_TOT);

    // Fork: padded-CSR scatter (src/dst only) || W-prep + projection GEMM.
    cudaStream_t s2;
    cudaStreamCreateWithFlags(&s2, cudaStreamNonBlocking);
    cudaEvent_t evFork, evJoin;
    cudaEventCreateWithFlags(&evFork, cudaEventDisableTiming);
    cudaEventCreateWithFlags(&evJoin, cudaEventDisableTiming);

    cudaEventRecord(evFork, 0);
    cudaStreamWaitEvent(s2, evFork, 0);

    scatter_kernel<<<(N_EDGES / 4 + 255) / 256, 256, 0, s2>>>(src, dst);         // s2
    cudaEventRecord(evJoin, s2);

    wprep_kernel<<<(128 * F_IN + 255) / 256, 256>>>(Wsrc, Wdst);                 // 1
    proj_mma_kernel<<<(N_NODES + 127) / 128, 256, SM_TOT>>>(feat, bsrc, bdst);   // 2
    sep_kernel<<<1, 32>>>();                                                     // 3

    cudaStreamWaitEvent(0, evJoin, 0);
    agg_kernel<<<(N_NODES * 32 + 255) / 256, 256>>>(out, attn);                  // 4
}

// round 15
// speedup vs baseline: 1.0600x; 1.0600x over previous
#include <cuda_runtime.h>
#include <cuda_bf16.h>
#include <cstdint>

#define N_NODES 50000
#define N_EDGES 800000
#define F_IN    256
#define NH      4
#define HD      64
#define SLOT_W  64

// ---------------- scratch (device globals; no allocs allowed) ----------------
__device__ float g_hsrc[N_NODES * HD];
__device__ float g_hdst[N_NODES * HD];
__device__ int   g_deg[N_NODES];              // starts 0; agg re-zeroes after use
__device__ int   g_slots[N_NODES * SLOT_W];   // padded CSR payload: src ids

// ---------------- padded-CSR scatter (single kernel, no init/scan) ----------------
__global__ void scatter_kernel(const int* __restrict__ src, const int* __restrict__ dst) {
    int base = (blockIdx.x * blockDim.x + threadIdx.x) * 4;
    if (base + 3 < N_EDGES) {
        int4 d = *(const int4*)(dst + base);
        int4 s = *(const int4*)(src + base);
        int p0 = atomicAdd(&g_deg[d.x], 1);
        int p1 = atomicAdd(&g_deg[d.y], 1);
        int p2 = atomicAdd(&g_deg[d.z], 1);
        int p3 = atomicAdd(&g_deg[d.w], 1);
        g_slots[d.x * SLOT_W + p0] = s.x;
        g_slots[d.y * SLOT_W + p1] = s.y;
        g_slots[d.z * SLOT_W + p2] = s.z;
        g_slots[d.w * SLOT_W + p3] = s.w;
    } else {
        for (int e = base; e < N_EDGES; e++) {
            int p = atomicAdd(&g_deg[dst[e]], 1);
            g_slots[dst[e] * SLOT_W + p] = src[e];
        }
    }
}

// ---------------- helpers ----------------
__device__ __forceinline__ uint32_t smem_u32(const void* p) {
    uint32_t a;
    asm("{ .reg .u64 t; cvta.to.shared.u64 t, %1; cvt.u32.u64 %0, t; }" : "=r"(a) : "l"(p));
    return a;
}
__device__ __forceinline__ void ldsm4(unsigned r[4], uint32_t a) {
    asm volatile("ldmatrix.sync.aligned.m8n8.x4.shared.b16 {%0,%1,%2,%3}, [%4];"
                 : "=r"(r[0]), "=r"(r[1]), "=r"(r[2]), "=r"(r[3]) : "r"(a));
}
__device__ __forceinline__ void mma_bf16(float c[4], const unsigned a[4], const unsigned b[2]) {
    asm volatile(
        "mma.sync.aligned.m16n8k16.row.col.f32.bf16.bf16.f32 "
        "{%0,%1,%2,%3}, {%4,%5,%6,%7}, {%8,%9}, {%0,%1,%2,%3};"
        : "+f"(c[0]), "+f"(c[1]), "+f"(c[2]), "+f"(c[3])
        : "r"(a[0]), "r"(a[1]), "r"(a[2]), "r"(a[3]), "r"(b[0]), "r"(b[1]));
}
__device__ __forceinline__ void cvt8(float4 a, float4 b, uint4& hi, uint4& lo) {
    float xs[8] = {a.x, a.y, a.z, a.w, b.x, b.y, b.z, b.w};
    unsigned h[4], l[4];
    #pragma unroll
    for (int i = 0; i < 4; i++) {
        float x = xs[2 * i], y = xs[2 * i + 1];
        __nv_bfloat16 hx = __float2bfloat16_rn(x);
        __nv_bfloat16 hy = __float2bfloat16_rn(y);
        __nv_bfloat16 lx = __float2bfloat16_rn(x - __bfloat162float(hx));
        __nv_bfloat16 ly = __float2bfloat16_rn(y - __bfloat162float(hy));
        unsigned short uhx = *(unsigned short*)&hx, uhy = *(unsigned short*)&hy;
        unsigned short ulx = *(unsigned short*)&lx, uly = *(unsigned short*)&ly;
        h[i] = (unsigned)uhx | ((unsigned)uhy << 16);
        l[i] = (unsigned)ulx | ((unsigned)uly << 16);
    }
    hi = make_uint4(h[0], h[1], h[2], h[3]);
    lo = make_uint4(l[0], l[1], l[2], l[3]);
}

// ---------------- HMMA bf16-split projection GEMM v2 (round-9/12 proven) ----------------
#define RSB2   80
#define TILE2  10240
#define STG2   40960
#define SM_TOT 81920

__global__ __launch_bounds__(256, 2)
void proj_mma_kernel(const float* __restrict__ feat,
                     const float* __restrict__ Wsrc, const float* __restrict__ bsrc,
                     const float* __restrict__ Wdst, const float* __restrict__ bdst)
{
    extern __shared__ char smem[];
    const uint32_t sb = smem_u32(smem);
    const int tid  = threadIdx.x;
    const int wid  = tid >> 5, lane = tid & 31;
    const int warp_m = wid & 3;
    const int warp_n = wid >> 2;
    const int m0 = blockIdx.x * 128;

    float acc[2][8][4];
    #pragma unroll
    for (int mt = 0; mt < 2; mt++)
        #pragma unroll
        for (int nt = 0; nt < 8; nt++)
            #pragma unroll
            for (int j = 0; j < 4; j++) acc[mt][nt][j] = 0.0f;

    float4 pa[2][2], pb[2][2];

    #define LOAD_AB(c) do {                                                       \
        _Pragma("unroll")                                                         \
        for (int i = 0; i < 2; i++) {                                             \
            int t = tid + i * 256, row = t >> 2, seg = t & 3;                     \
            int node = m0 + row; if (node >= N_NODES) node = N_NODES - 1;         \
            const float* p = feat + (size_t)node * F_IN + (c) * 32 + seg * 8;     \
            pa[i][0] = *(const float4*)p; pa[i][1] = *(const float4*)(p + 4);     \
            const float* wr = (row < 64) ? (Wsrc + (size_t)row * F_IN)            \
                                         : (Wdst + (size_t)(row - 64) * F_IN);    \
            const float* q = wr + (c) * 32 + seg * 8;                             \
            pb[i][0] = *(const float4*)q; pb[i][1] = *(const float4*)(q + 4);     \
        } } while (0)

    #define STORE_AB(st) do {                                                     \
        _Pragma("unroll")                                                         \
        for (int i = 0; i < 2; i++) {                                             \
            int t = tid + i * 256, row = t >> 2, seg = t & 3;                     \
            uint32_t off = (uint32_t)((st) * STG2 + row * RSB2 + seg * 16);       \
            uint4 hi, lo;                                                         \
            cvt8(pa[i][0], pa[i][1], hi, lo);                                     \
            *(uint4*)(smem + off)         = hi;                                   \
            *(uint4*)(smem + TILE2 + off) = lo;                                   \
            cvt8(pb[i][0], pb[i][1], hi, lo);                                     \
            *(uint4*)(smem + 2 * TILE2 + off) = hi;                               \
            *(uint4*)(smem + 3 * TILE2 + off) = lo;                               \
        } } while (0)

    LOAD_AB(0);
    STORE_AB(0);
    __syncthreads();

    const uint32_t a_off = (uint32_t)((warp_m * 32 + (lane & 15)) * RSB2 + (lane >> 4) * 16);
    const uint32_t b_off = (uint32_t)((warp_n * 64 + (lane & 7) + ((lane >> 4) & 1) * 8) * RSB2 +
                                      ((lane >> 3) & 1) * 16);

    for (int c = 0; c < 8; c++) {
        const uint32_t st = (uint32_t)(c & 1) * STG2;
        if (c < 7) LOAD_AB(c + 1);

        #pragma unroll
        for (int ks = 0; ks < 2; ks++) {
            unsigned ah[2][4], al[2][4];
            #pragma unroll
            for (int mt = 0; mt < 2; mt++) {
                ldsm4(ah[mt], sb + st + a_off + (uint32_t)(mt * 16 * RSB2 + ks * 32));
                ldsm4(al[mt], sb + st + TILE2 + a_off + (uint32_t)(mt * 16 * RSB2 + ks * 32));
            }
            unsigned bh[4][4], bl[4][4];
            #pragma unroll
            for (int p = 0; p < 4; p++) {
                ldsm4(bh[p], sb + st + 2 * TILE2 + b_off + (uint32_t)(p * 16 * RSB2 + ks * 32));
                ldsm4(bl[p], sb + st + 3 * TILE2 + b_off + (uint32_t)(p * 16 * RSB2 + ks * 32));
            }
            #pragma unroll
            for (int mt = 0; mt < 2; mt++)
                #pragma unroll
                for (int nt = 0; nt < 8; nt++) {
                    const unsigned* bhf = &bh[nt >> 1][(nt & 1) * 2];
                    const unsigned* blf = &bl[nt >> 1][(nt & 1) * 2];
                    mma_bf16(acc[mt][nt], ah[mt], bhf);
                    mma_bf16(acc[mt][nt], ah[mt], blf);
                    mma_bf16(acc[mt][nt], al[mt], bhf);
                }
        }
        if (c < 7) STORE_AB((c + 1) & 1);
        __syncthreads();
    }

    #pragma unroll
    for (int mt = 0; mt < 2; mt++)
        #pragma unroll
        for (int nt = 0; nt < 8; nt++) {
            int row = warp_m * 32 + mt * 16 + (lane >> 2);
            int o   = warp_n * 64 + nt * 8 + (lane & 3) * 2;
            float* buf; int col;
            float b0, b1;
            if (o < 64) { col = o;      buf = g_hsrc; b0 = bsrc[col]; b1 = bsrc[col + 1]; }
            else        { col = o - 64; buf = g_hdst; b0 = bdst[col]; b1 = bdst[col + 1]; }
            int n0 = m0 + row, n1 = m0 + row + 8;
            if (n0 < N_NODES)
                *(float2*)(buf + (size_t)n0 * HD + col) =
                    make_float2(acc[mt][nt][0] + b0, acc[mt][nt][1] + b1);
            if (n1 < N_NODES)
                *(float2*)(buf + (size_t)n1 * HD + col) =
                    make_float2(acc[mt][nt][2] + b0, acc[mt][nt][3] + b1);
        }
}

// ---------------- aggregation (round-12 proven config; slot loads via __ldg) ----------------
__global__ __launch_bounds__(256) void agg_kernel(float* __restrict__ out,
                                                  const float* __restrict__ attn)
{
    int warp = (blockIdx.x * blockDim.x + threadIdx.x) >> 5;
    int lane = threadIdx.x & 31;
    if (warp >= N_NODES) return;
    const int d    = warp;
    const int half = lane >> 4;
    const int l16  = lane & 15;

    float4 er = ((const float4*)(g_hdst + (size_t)d * HD))[l16];
    float4 aw = ((const float4*)attn)[l16];

    const int  cnt  = g_deg[d];
    const int* slot = g_slots + d * SLOT_W + lane;

    float4 acc = make_float4(0.f, 0.f, 0.f, 0.f);
    float  s   = 0.f;

    for (int base = 0; base < cnt; base += 32) {
        int m = cnt - base; if (m > 32) m = 32;
        int sn_l = (lane < m) ? __ldg(slot + base) : 0;

        #pragma unroll 2
        for (int i = 0; i < m; i += 2) {
            int   eidx  = i + half;
            float valid = (eidx < m) ? 1.0f : 0.0f;
            int   sn    = __shfl_sync(0xFFFFFFFFu, sn_l, eidx & 31);
            float4 el = ((const float4*)(g_hsrc + (size_t)sn * HD))[l16];
            float vx = el.x + er.x, vy = el.y + er.y,
                  vz = el.z + er.z, vw = el.w + er.w;
            vx = fmaxf(vx, 0.f) + 0.2f * fminf(vx, 0.f);
            vy = fmaxf(vy, 0.f) + 0.2f * fminf(vy, 0.f);
            vz = fmaxf(vz, 0.f) + 0.2f * fminf(vz, 0.f);
            vw = fmaxf(vw, 0.f) + 0.2f * fminf(vw, 0.f);
            float p = vx * aw.x + vy * aw.y + vz * aw.z + vw * aw.w;
            p += __shfl_xor_sync(0xFFFFFFFFu, p, 1);
            p += __shfl_xor_sync(0xFFFFFFFFu, p, 2);
            float a = __expf(p) * valid;
            acc.x += a * el.x;
            acc.y += a * el.y;
            acc.z += a * el.z;
            acc.w += a * el.w;
            s     += a;
        }
    }

    acc.x += __shfl_xor_sync(0xFFFFFFFFu, acc.x, 16);
    acc.y += __shfl_xor_sync(0xFFFFFFFFu, acc.y, 16);
    acc.z += __shfl_xor_sync(0xFFFFFFFFu, acc.z, 16);
    acc.w += __shfl_xor_sync(0xFFFFFFFFu, acc.w, 16);
    s     += __shfl_xor_sync(0xFFFFFFFFu, s, 16);

    if (lane == 0) g_deg[d] = 0;   // restore invariant for next graph replay

    if (half == 0) {
        float inv = (s > 0.f) ? (1.f / s) : 0.f;
        ((float4*)(out + (size_t)d * HD))[l16] =
            make_float4(acc.x * inv, acc.y * inv, acc.z * inv, acc.w * inv);
    }
}

extern "C" void kernel_launch(void* const* d_in, const int* in_sizes, int n_in,
                              void* d_out, int out_size)
{
    const float* feat = (const float*)d_in[0];
    const int*   src  = (const int*)d_in[1];
    const int*   dst  = (const int*)d_in[2];
    const float* Wsrc = (const float*)d_in[3];
    const float* bsrc = (const float*)d_in[4];
    const float* Wdst = (const float*)d_in[5];
    const float* bdst = (const float*)d_in[6];
    const float* attn = (const float*)d_in[7];
    float* out = (float*)d_out;

    cudaFuncSetAttribute(proj_mma_kernel, cudaFuncAttributeMaxDynamicSharedMemorySize, SM_TOT);

    // Fork: padded-CSR scatter (src/dst only) || projection GEMM (feat/W only).
    cudaStream_t s2;
    cudaStreamCreateWithFlags(&s2, cudaStreamNonBlocking);
    cudaEvent_t evFork, evJoin;
    cudaEventCreateWithFlags(&evFork, cudaEventDisableTiming);
    cudaEventCreateWithFlags(&evJoin, cudaEventDisableTiming);

    cudaEventRecord(evFork, 0);
    cudaStreamWaitEvent(s2, evFork, 0);

    scatter_kernel<<<(N_EDGES / 4 + 255) / 256, 256, 0, s2>>>(src, dst);
    cudaEventRecord(evJoin, s2);

    proj_mma_kernel<<<(N_NODES + 127) / 128, 256, SM_TOT>>>(feat, Wsrc, bsrc, Wdst, bdst);

    cudaStreamWaitEvent(0, evJoin, 0);
    agg_kernel<<<(N_NODES * 32 + 255) / 256, 256>>>(out, attn);
}

// round 16
// speedup vs baseline: 1.1423x; 1.0776x over previous
#include <cuda_runtime.h>
#include <cuda_bf16.h>
#include <cstdint>

#define N_NODES 50000
#define N_EDGES 800000
#define F_IN    256
#define NH      4
#define HD      64
#define SLOT_W  64

// ---------------- scratch (device globals; no allocs allowed) ----------------
__device__ float g_hsrc[N_NODES * HD];
__device__ float g_hdst[N_NODES * HD];
__device__ int   g_deg[N_NODES];              // starts 0; agg re-zeroes after use
__device__ int   g_slots[N_NODES * SLOT_W];   // padded CSR payload: src ids

// ---------------- padded-CSR scatter (single kernel, no init/scan) ----------------
__global__ void scatter_kernel(const int* __restrict__ src, const int* __restrict__ dst) {
    int base = (blockIdx.x * blockDim.x + threadIdx.x) * 4;
    if (base + 3 < N_EDGES) {
        int4 d = *(const int4*)(dst + base);
        int4 s = *(const int4*)(src + base);
        int p0 = atomicAdd(&g_deg[d.x], 1);
        int p1 = atomicAdd(&g_deg[d.y], 1);
        int p2 = atomicAdd(&g_deg[d.z], 1);
        int p3 = atomicAdd(&g_deg[d.w], 1);
        g_slots[d.x * SLOT_W + p0] = s.x;
        g_slots[d.y * SLOT_W + p1] = s.y;
        g_slots[d.z * SLOT_W + p2] = s.z;
        g_slots[d.w * SLOT_W + p3] = s.w;
    } else {
        for (int e = base; e < N_EDGES; e++) {
            int p = atomicAdd(&g_deg[dst[e]], 1);
            g_slots[dst[e] * SLOT_W + p] = src[e];
        }
    }
}

// ---------------- helpers ----------------
__device__ __forceinline__ uint32_t smem_u32(const void* p) {
    uint32_t a;
    asm("{ .reg .u64 t; cvta.to.shared.u64 t, %1; cvt.u32.u64 %0, t; }" : "=r"(a) : "l"(p));
    return a;
}
__device__ __forceinline__ void ldsm4(unsigned r[4], uint32_t a) {
    asm volatile("ldmatrix.sync.aligned.m8n8.x4.shared.b16 {%0,%1,%2,%3}, [%4];"
                 : "=r"(r[0]), "=r"(r[1]), "=r"(r[2]), "=r"(r[3]) : "r"(a));
}
__device__ __forceinline__ void mma_bf16(float c[4], const unsigned a[4], const unsigned b[2]) {
    asm volatile(
        "mma.sync.aligned.m16n8k16.row.col.f32.bf16.bf16.f32 "
        "{%0,%1,%2,%3}, {%4,%5,%6,%7}, {%8,%9}, {%0,%1,%2,%3};"
        : "+f"(c[0]), "+f"(c[1]), "+f"(c[2]), "+f"(c[3])
        : "r"(a[0]), "r"(a[1]), "r"(a[2]), "r"(a[3]), "r"(b[0]), "r"(b[1]));
}
__device__ __forceinline__ void cvt8(float4 a, float4 b, uint4& hi, uint4& lo) {
    float xs[8] = {a.x, a.y, a.z, a.w, b.x, b.y, b.z, b.w};
    unsigned h[4], l[4];
    #pragma unroll
    for (int i = 0; i < 4; i++) {
        float x = xs[2 * i], y = xs[2 * i + 1];
        __nv_bfloat16 hx = __float2bfloat16_rn(x);
        __nv_bfloat16 hy = __float2bfloat16_rn(y);
        __nv_bfloat16 lx = __float2bfloat16_rn(x - __bfloat162float(hx));
        __nv_bfloat16 ly = __float2bfloat16_rn(y - __bfloat162float(hy));
        unsigned short uhx = *(unsigned short*)&hx, uhy = *(unsigned short*)&hy;
        unsigned short ulx = *(unsigned short*)&lx, uly = *(unsigned short*)&ly;
        h[i] = (unsigned)uhx | ((unsigned)uhy << 16);
        l[i] = (unsigned)ulx | ((unsigned)uly << 16);
    }
    hi = make_uint4(h[0], h[1], h[2], h[3]);
    lo = make_uint4(l[0], l[1], l[2], l[3]);
}

// ---------------- HMMA bf16-split projection GEMM v2.2 ----------------
// Round-12 proven structure + L2 prefetch of chunk c+2's A (feat) rows:
// converts the exposed A-LDG latency from DRAM (577cyc) to L2 (~250cyc),
// which the per-chunk MMA compute covers. Zero register cost.
#define RSB2   80
#define TILE2  10240
#define STG2   40960
#define SM_TOT 81920

__global__ __launch_bounds__(256, 2)
void proj_mma_kernel(const float* __restrict__ feat,
                     const float* __restrict__ Wsrc, const float* __restrict__ bsrc,
                     const float* __restrict__ Wdst, const float* __restrict__ bdst)
{
    extern __shared__ char smem[];
    const uint32_t sb = smem_u32(smem);
    const int tid  = threadIdx.x;
    const int wid  = tid >> 5, lane = tid & 31;
    const int warp_m = wid & 3;
    const int warp_n = wid >> 2;
    const int m0 = blockIdx.x * 128;

    float acc[2][8][4];
    #pragma unroll
    for (int mt = 0; mt < 2; mt++)
        #pragma unroll
        for (int nt = 0; nt < 8; nt++)
            #pragma unroll
            for (int j = 0; j < 4; j++) acc[mt][nt][j] = 0.0f;

    float4 pa[2][2], pb[2][2];

    #define LOAD_AB(c) do {                                                       \
        _Pragma("unroll")                                                         \
        for (int i = 0; i < 2; i++) {                                             \
            int t = tid + i * 256, row = t >> 2, seg = t & 3;                     \
            int node = m0 + row; if (node >= N_NODES) node = N_NODES - 1;         \
            const float* p = feat + (size_t)node * F_IN + (c) * 32 + seg * 8;     \
            pa[i][0] = *(const float4*)p; pa[i][1] = *(const float4*)(p + 4);     \
            const float* wr = (row < 64) ? (Wsrc + (size_t)row * F_IN)            \
                                         : (Wdst + (size_t)(row - 64) * F_IN);    \
            const float* q = wr + (c) * 32 + seg * 8;                             \
            pb[i][0] = *(const float4*)q; pb[i][1] = *(const float4*)(q + 4);     \
        } } while (0)

    // L2 prefetch of chunk (c)'s A rows (hint; covers this thread's 32B)
    #define PREF_A(c) do {                                                        \
        _Pragma("unroll")                                                         \
        for (int i = 0; i < 2; i++) {                                             \
            int t = tid + i * 256, row = t >> 2, seg = t & 3;                     \
            int node = m0 + row; if (node >= N_NODES) node = N_NODES - 1;         \
            const float* p = feat + (size_t)node * F_IN + (c) * 32 + seg * 8;     \
            asm volatile("prefetch.global.L2 [%0];" :: "l"(p));                   \
        } } while (0)

    #define STORE_AB(st) do {                                                     \
        _Pragma("unroll")                                                         \
        for (int i = 0; i < 2; i++) {                                             \
            int t = tid + i * 256, row = t >> 2, seg = t & 3;                     \
            uint32_t off = (uint32_t)((st) * STG2 + row * RSB2 + seg * 16);       \
            uint4 hi, lo;                                                         \
            cvt8(pa[i][0], pa[i][1], hi, lo);                                     \
            *(uint4*)(smem + off)         = hi;                                   \
            *(uint4*)(smem + TILE2 + off) = lo;                                   \
            cvt8(pb[i][0], pb[i][1], hi, lo);                                     \
            *(uint4*)(smem + 2 * TILE2 + off) = hi;                               \
            *(uint4*)(smem + 3 * TILE2 + off) = lo;                               \
        } } while (0)

    LOAD_AB(0);
    PREF_A(1);
    PREF_A(2);
    STORE_AB(0);
    __syncthreads();

    const uint32_t a_off = (uint32_t)((warp_m * 32 + (lane & 15)) * RSB2 + (lane >> 4) * 16);
    const uint32_t b_off = (uint32_t)((warp_n * 64 + (lane & 7) + ((lane >> 4) & 1) * 8) * RSB2 +
                                      ((lane >> 3) & 1) * 16);

    for (int c = 0; c < 8; c++) {
        const uint32_t st = (uint32_t)(c & 1) * STG2;
        if (c < 7) LOAD_AB(c + 1);
        if (c < 6) PREF_A(c + 2);

        #pragma unroll
        for (int ks = 0; ks < 2; ks++) {
            unsigned ah[2][4], al[2][4];
            #pragma unroll
            for (int mt = 0; mt < 2; mt++) {
                ldsm4(ah[mt], sb + st + a_off + (uint32_t)(mt * 16 * RSB2 + ks * 32));
                ldsm4(al[mt], sb + st + TILE2 + a_off + (uint32_t)(mt * 16 * RSB2 + ks * 32));
            }
            unsigned bh[4][4], bl[4][4];
            #pragma unroll
            for (int p = 0; p < 4; p++) {
                ldsm4(bh[p], sb + st + 2 * TILE2 + b_off + (uint32_t)(p * 16 * RSB2 + ks * 32));
                ldsm4(bl[p], sb + st + 3 * TILE2 + b_off + (uint32_t)(p * 16 * RSB2 + ks * 32));
            }
            #pragma unroll
            for (int mt = 0; mt < 2; mt++)
                #pragma unroll
                for (int nt = 0; nt < 8; nt++) {
                    const unsigned* bhf = &bh[nt >> 1][(nt & 1) * 2];
                    const unsigned* blf = &bl[nt >> 1][(nt & 1) * 2];
                    mma_bf16(acc[mt][nt], ah[mt], bhf);
                    mma_bf16(acc[mt][nt], ah[mt], blf);
                    mma_bf16(acc[mt][nt], al[mt], bhf);
                }
        }
        if (c < 7) STORE_AB((c + 1) & 1);
        __syncthreads();
    }

    #pragma unroll
    for (int mt = 0; mt < 2; mt++)
        #pragma unroll
        for (int nt = 0; nt < 8; nt++) {
            int row = warp_m * 32 + mt * 16 + (lane >> 2);
            int o   = warp_n * 64 + nt * 8 + (lane & 3) * 2;
            float* buf; int col;
            float b0, b1;
            if (o < 64) { col = o;      buf = g_hsrc; b0 = bsrc[col]; b1 = bsrc[col + 1]; }
            else        { col = o - 64; buf = g_hdst; b0 = bdst[col]; b1 = bdst[col + 1]; }
            int n0 = m0 + row, n1 = m0 + row + 8;
            if (n0 < N_NODES)
                *(float2*)(buf + (size_t)n0 * HD + col) =
                    make_float2(acc[mt][nt][0] + b0, acc[mt][nt][1] + b1);
            if (n1 < N_NODES)
                *(float2*)(buf + (size_t)n1 * HD + col) =
                    make_float2(acc[mt][nt][2] + b0, acc[mt][nt][3] + b1);
        }
}

// ---------------- aggregation (round-15 proven config) ----------------
__global__ __launch_bounds__(256) void agg_kernel(float* __restrict__ out,
                                                  const float* __restrict__ attn)
{
    int warp = (blockIdx.x * blockDim.x + threadIdx.x) >> 5;
    int lane = threadIdx.x & 31;
    if (warp >= N_NODES) return;
    const int d    = warp;
    const int half = lane >> 4;
    const int l16  = lane & 15;

    float4 er = ((const float4*)(g_hdst + (size_t)d * HD))[l16];
    float4 aw = ((const float4*)attn)[l16];

    const int  cnt  = g_deg[d];
    const int* slot = g_slots + d * SLOT_W + lane;

    float4 acc = make_float4(0.f, 0.f, 0.f, 0.f);
    float  s   = 0.f;

    for (int base = 0; base < cnt; base += 32) {
        int m = cnt - base; if (m > 32) m = 32;
        int sn_l = (lane < m) ? __ldg(slot + base) : 0;

        #pragma unroll 2
        for (int i = 0; i < m; i += 2) {
            int   eidx  = i + half;
            float valid = (eidx < m) ? 1.0f : 0.0f;
            int   sn    = __shfl_sync(0xFFFFFFFFu, sn_l, eidx & 31);
            float4 el = ((const float4*)(g_hsrc + (size_t)sn * HD))[l16];
            float vx = el.x + er.x, vy = el.y + er.y,
                  vz = el.z + er.z, vw = el.w + er.w;
            vx = fmaxf(vx, 0.f) + 0.2f * fminf(vx, 0.f);
            vy = fmaxf(vy, 0.f) + 0.2f * fminf(vy, 0.f);
            vz = fmaxf(vz, 0.f) + 0.2f * fminf(vz, 0.f);
            vw = fmaxf(vw, 0.f) + 0.2f * fminf(vw, 0.f);
            float p = vx * aw.x + vy * aw.y + vz * aw.z + vw * aw.w;
            p += __shfl_xor_sync(0xFFFFFFFFu, p, 1);
            p += __shfl_xor_sync(0xFFFFFFFFu, p, 2);
            float a = __expf(p) * valid;
            acc.x += a * el.x;
            acc.y += a * el.y;
            acc.z += a * el.z;
            acc.w += a * el.w;
            s     += a;
        }
    }

    acc.x += __shfl_xor_sync(0xFFFFFFFFu, acc.x, 16);
    acc.y += __shfl_xor_sync(0xFFFFFFFFu, acc.y, 16);
    acc.z += __shfl_xor_sync(0xFFFFFFFFu, acc.z, 16);
    acc.w += __shfl_xor_sync(0xFFFFFFFFu, acc.w, 16);
    s     += __shfl_xor_sync(0xFFFFFFFFu, s, 16);

    if (lane == 0) g_deg[d] = 0;   // restore invariant for next graph replay

    if (half == 0) {
        float inv = (s > 0.f) ? (1.f / s) : 0.f;
        ((float4*)(out + (size_t)d * HD))[l16] =
            make_float4(acc.x * inv, acc.y * inv, acc.z * inv, acc.w * inv);
    }
}

extern "C" void kernel_launch(void* const* d_in, const int* in_sizes, int n_in,
                              void* d_out, int out_size)
{
    const float* feat = (const float*)d_in[0];
    const int*   src  = (const int*)d_in[1];
    const int*   dst  = (const int*)d_in[2];
    const float* Wsrc = (const float*)d_in[3];
    const float* bsrc = (const float*)d_in[4];
    const float* Wdst = (const float*)d_in[5];
    const float* bdst = (const float*)d_in[6];
    const float* attn = (const float*)d_in[7];
    float* out = (float*)d_out;

    cudaFuncSetAttribute(proj_mma_kernel, cudaFuncAttributeMaxDynamicSharedMemorySize, SM_TOT);

    // Fork: padded-CSR scatter (src/dst only) || projection GEMM (feat/W only).
    cudaStream_t s2;
    cudaStreamCreateWithFlags(&s2, cudaStreamNonBlocking);
    cudaEvent_t evFork, evJoin;
    cudaEventCreateWithFlags(&evFork, cudaEventDisableTiming);
    cudaEventCreateWithFlags(&evJoin, cudaEventDisableTiming);

    cudaEventRecord(evFork, 0);
    cudaStreamWaitEvent(s2, evFork, 0);

    scatter_kernel<<<(N_EDGES / 4 + 255) / 256, 256, 0, s2>>>(src, dst);
    cudaEventRecord(evJoin, s2);

    proj_mma_kernel<<<(N_NODES + 127) / 128, 256, SM_TOT>>>(feat, Wsrc, bsrc, Wdst, bdst);

    cudaStreamWaitEvent(0, evJoin, 0);
    agg_kernel<<<(N_NODES * 32 + 255) / 256, 256>>>(out, attn);
}

// round 17
// speedup vs baseline: 1.1462x; 1.0034x over previous
#include <cuda_runtime.h>
#include <cuda_bf16.h>
#include <cstdint>

#define N_NODES 50000
#define N_EDGES 800000
#define F_IN    256
#define NH      4
#define HD      64
#define SLOT_W  64

typedef unsigned long long u64t;

// ---------------- scratch (device globals; no allocs allowed) ----------------
__device__ float g_hsrc[N_NODES * HD];
__device__ float g_hdst[N_NODES * HD];
__device__ int   g_deg[N_NODES];              // starts 0; agg re-zeroes after use
__device__ int   g_slots[N_NODES * SLOT_W];   // padded CSR payload: src ids

// ---------------- padded-CSR scatter (single kernel, no init/scan) ----------------
__global__ void scatter_kernel(const int* __restrict__ src, const int* __restrict__ dst) {
    int base = (blockIdx.x * blockDim.x + threadIdx.x) * 4;
    if (base + 3 < N_EDGES) {
        int4 d = *(const int4*)(dst + base);
        int4 s = *(const int4*)(src + base);
        int p0 = atomicAdd(&g_deg[d.x], 1);
        int p1 = atomicAdd(&g_deg[d.y], 1);
        int p2 = atomicAdd(&g_deg[d.z], 1);
        int p3 = atomicAdd(&g_deg[d.w], 1);
        g_slots[d.x * SLOT_W + p0] = s.x;
        g_slots[d.y * SLOT_W + p1] = s.y;
        g_slots[d.z * SLOT_W + p2] = s.z;
        g_slots[d.w * SLOT_W + p3] = s.w;
    } else {
        for (int e = base; e < N_EDGES; e++) {
            int p = atomicAdd(&g_deg[dst[e]], 1);
            g_slots[dst[e] * SLOT_W + p] = src[e];
        }
    }
}

// ---------------- helpers ----------------
__device__ __forceinline__ uint32_t smem_u32(const void* p) {
    uint32_t a;
    asm("{ .reg .u64 t; cvta.to.shared.u64 t, %1; cvt.u32.u64 %0, t; }" : "=r"(a) : "l"(p));
    return a;
}
__device__ __forceinline__ void ldsm4(unsigned r[4], uint32_t a) {
    asm volatile("ldmatrix.sync.aligned.m8n8.x4.shared.b16 {%0,%1,%2,%3}, [%4];"
                 : "=r"(r[0]), "=r"(r[1]), "=r"(r[2]), "=r"(r[3]) : "r"(a));
}
__device__ __forceinline__ void mma_bf16(float c[4], const unsigned a[4], const unsigned b[2]) {
    asm volatile(
        "mma.sync.aligned.m16n8k16.row.col.f32.bf16.bf16.f32 "
        "{%0,%1,%2,%3}, {%4,%5,%6,%7}, {%8,%9}, {%0,%1,%2,%3};"
        : "+f"(c[0]), "+f"(c[1]), "+f"(c[2]), "+f"(c[3])
        : "r"(a[0]), "r"(a[1]), "r"(a[2]), "r"(a[3]), "r"(b[0]), "r"(b[1]));
}
__device__ __forceinline__ void cvt8(float4 a, float4 b, uint4& hi, uint4& lo) {
    float xs[8] = {a.x, a.y, a.z, a.w, b.x, b.y, b.z, b.w};
    unsigned h[4], l[4];
    #pragma unroll
    for (int i = 0; i < 4; i++) {
        float x = xs[2 * i], y = xs[2 * i + 1];
        __nv_bfloat16 hx = __float2bfloat16_rn(x);
        __nv_bfloat16 hy = __float2bfloat16_rn(y);
        __nv_bfloat16 lx = __float2bfloat16_rn(x - __bfloat162float(hx));
        __nv_bfloat16 ly = __float2bfloat16_rn(y - __bfloat162float(hy));
        unsigned short uhx = *(unsigned short*)&hx, uhy = *(unsigned short*)&hy;
        unsigned short ulx = *(unsigned short*)&lx, uly = *(unsigned short*)&ly;
        h[i] = (unsigned)uhx | ((unsigned)uhy << 16);
        l[i] = (unsigned)ulx | ((unsigned)uly << 16);
    }
    hi = make_uint4(h[0], h[1], h[2], h[3]);
    lo = make_uint4(l[0], l[1], l[2], l[3]);
}

// packed f32x2 ops
#define F2_ADD(d, a, b)    asm("add.rn.f32x2 %0, %1, %2;" : "=l"(d) : "l"(a), "l"(b))
#define F2_MUL(d, a, b)    asm("mul.rn.f32x2 %0, %1, %2;" : "=l"(d) : "l"(a), "l"(b))
#define F2_FMA(d, a, b, c) asm("fma.rn.f32x2 %0, %1, %2, %3;" : "=l"(d) : "l"(a), "l"(b), "l"(c))
#define F2_UNPACK(lo, hi, v) asm("mov.b64 {%0, %1}, %2;" : "=f"(lo), "=f"(hi) : "l"(v))
#define F2_PACK1(d, x)       asm("mov.b64 %0, {%1, %1};" : "=l"(d) : "f"(x))

// ---------------- HMMA bf16-split projection GEMM v2.2 (R16 proven) ----------------
#define RSB2   80
#define TILE2  10240
#define STG2   40960
#define SM_TOT 81920

__global__ __launch_bounds__(256, 2)
void proj_mma_kernel(const float* __restrict__ feat,
                     const float* __restrict__ Wsrc, const float* __restrict__ bsrc,
                     const float* __restrict__ Wdst, const float* __restrict__ bdst)
{
    extern __shared__ char smem[];
    const uint32_t sb = smem_u32(smem);
    const int tid  = threadIdx.x;
    const int wid  = tid >> 5, lane = tid & 31;
    const int warp_m = wid & 3;
    const int warp_n = wid >> 2;
    const int m0 = blockIdx.x * 128;

    float acc[2][8][4];
    #pragma unroll
    for (int mt = 0; mt < 2; mt++)
        #pragma unroll
        for (int nt = 0; nt < 8; nt++)
            #pragma unroll
            for (int j = 0; j < 4; j++) acc[mt][nt][j] = 0.0f;

    float4 pa[2][2], pb[2][2];

    #define LOAD_AB(c) do {                                                       \
        _Pragma("unroll")                                                         \
        for (int i = 0; i < 2; i++) {                                             \
            int t = tid + i * 256, row = t >> 2, seg = t & 3;                     \
            int node = m0 + row; if (node >= N_NODES) node = N_NODES - 1;         \
            const float* p = feat + (size_t)node * F_IN + (c) * 32 + seg * 8;     \
            pa[i][0] = *(const float4*)p; pa[i][1] = *(const float4*)(p + 4);     \
            const float* wr = (row < 64) ? (Wsrc + (size_t)row * F_IN)            \
                                         : (Wdst + (size_t)(row - 64) * F_IN);    \
            const float* q = wr + (c) * 32 + seg * 8;                             \
            pb[i][0] = *(const float4*)q; pb[i][1] = *(const float4*)(q + 4);     \
        } } while (0)

    #define PREF_A(c) do {                                                        \
        _Pragma("unroll")                                                         \
        for (int i = 0; i < 2; i++) {                                             \
            int t = tid + i * 256, row = t >> 2, seg = t & 3;                     \
            int node = m0 + row; if (node >= N_NODES) node = N_NODES - 1;         \
            const float* p = feat + (size_t)node * F_IN + (c) * 32 + seg * 8;     \
            asm volatile("prefetch.global.L2 [%0];" :: "l"(p));                   \
        } } while (0)

    #define STORE_AB(st) do {                                                     \
        _Pragma("unroll")                                                         \
        for (int i = 0; i < 2; i++) {                                             \
            int t = tid + i * 256, row = t >> 2, seg = t & 3;                     \
            uint32_t off = (uint32_t)((st) * STG2 + row * RSB2 + seg * 16);       \
            uint4 hi, lo;                                                         \
            cvt8(pa[i][0], pa[i][1], hi, lo);                                     \
            *(uint4*)(smem + off)         = hi;                                   \
            *(uint4*)(smem + TILE2 + off) = lo;                                   \
            cvt8(pb[i][0], pb[i][1], hi, lo);                                     \
            *(uint4*)(smem + 2 * TILE2 + off) = hi;                               \
            *(uint4*)(smem + 3 * TILE2 + off) = lo;                               \
        } } while (0)

    LOAD_AB(0);
    PREF_A(1);
    PREF_A(2);
    STORE_AB(0);
    __syncthreads();

    const uint32_t a_off = (uint32_t)((warp_m * 32 + (lane & 15)) * RSB2 + (lane >> 4) * 16);
    const uint32_t b_off = (uint32_t)((warp_n * 64 + (lane & 7) + ((lane >> 4) & 1) * 8) * RSB2 +
                                      ((lane >> 3) & 1) * 16);

    for (int c = 0; c < 8; c++) {
        const uint32_t st = (uint32_t)(c & 1) * STG2;
        if (c < 7) LOAD_AB(c + 1);
        if (c < 6) PREF_A(c + 2);

        #pragma unroll
        for (int ks = 0; ks < 2; ks++) {
            unsigned ah[2][4], al[2][4];
            #pragma unroll
            for (int mt = 0; mt < 2; mt++) {
                ldsm4(ah[mt], sb + st + a_off + (uint32_t)(mt * 16 * RSB2 + ks * 32));
                ldsm4(al[mt], sb + st + TILE2 + a_off + (uint32_t)(mt * 16 * RSB2 + ks * 32));
            }
            unsigned bh[4][4], bl[4][4];
            #pragma unroll
            for (int p = 0; p < 4; p++) {
                ldsm4(bh[p], sb + st + 2 * TILE2 + b_off + (uint32_t)(p * 16 * RSB2 + ks * 32));
                ldsm4(bl[p], sb + st + 3 * TILE2 + b_off + (uint32_t)(p * 16 * RSB2 + ks * 32));
            }
            #pragma unroll
            for (int mt = 0; mt < 2; mt++)
                #pragma unroll
                for (int nt = 0; nt < 8; nt++) {
                    const unsigned* bhf = &bh[nt >> 1][(nt & 1) * 2];
                    const unsigned* blf = &bl[nt >> 1][(nt & 1) * 2];
                    mma_bf16(acc[mt][nt], ah[mt], bhf);
                    mma_bf16(acc[mt][nt], ah[mt], blf);
                    mma_bf16(acc[mt][nt], al[mt], bhf);
                }
        }
        if (c < 7) STORE_AB((c + 1) & 1);
        __syncthreads();
    }

    #pragma unroll
    for (int mt = 0; mt < 2; mt++)
        #pragma unroll
        for (int nt = 0; nt < 8; nt++) {
            int row = warp_m * 32 + mt * 16 + (lane >> 2);
            int o   = warp_n * 64 + nt * 8 + (lane & 3) * 2;
            float* buf; int col;
            float b0, b1;
            if (o < 64) { col = o;      buf = g_hsrc; b0 = bsrc[col]; b1 = bsrc[col + 1]; }
            else        { col = o - 64; buf = g_hdst; b0 = bdst[col]; b1 = bdst[col + 1]; }
            int n0 = m0 + row, n1 = m0 + row + 8;
            if (n0 < N_NODES)
                *(float2*)(buf + (size_t)n0 * HD + col) =
                    make_float2(acc[mt][nt][0] + b0, acc[mt][nt][1] + b1);
            if (n1 < N_NODES)
                *(float2*)(buf + (size_t)n1 * HD + col) =
                    make_float2(acc[mt][nt][2] + b0, acc[mt][nt][3] + b1);
        }
}

// ---------------- aggregation v4: packed f32x2 math ----------------
// lrelu(v) = 0.6*v + 0.4*|v|  (exact for the two linear branches up to rounding)
__global__ __launch_bounds__(256) void agg_kernel(float* __restrict__ out,
                                                  const float* __restrict__ attn)
{
    int warp = (blockIdx.x * blockDim.x + threadIdx.x) >> 5;
    int lane = threadIdx.x & 31;
    if (warp >= N_NODES) return;
    const int d    = warp;
    const int half = lane >> 4;
    const int l16  = lane & 15;

    ulonglong2 er2 = ((const ulonglong2*)(g_hdst + (size_t)d * HD))[l16];
    ulonglong2 aw2 = ((const ulonglong2*)attn)[l16];

    const unsigned f06 = __float_as_uint(0.6f);
    const unsigned f04 = __float_as_uint(0.4f);
    const u64t c06 = (u64t)f06 | ((u64t)f06 << 32);
    const u64t c04 = (u64t)f04 | ((u64t)f04 << 32);
    const u64t amask = 0x7FFFFFFF7FFFFFFFull;

    const int  cnt  = g_deg[d];
    const int* slot = g_slots + d * SLOT_W + lane;

    u64t acc01 = 0ull, acc23 = 0ull;
    float s = 0.f;

    for (int base = 0; base < cnt; base += 32) {
        int m = cnt - base; if (m > 32) m = 32;
        int sn_l = (lane < m) ? __ldg(slot + base) : 0;

        #pragma unroll 2
        for (int i = 0; i < m; i += 2) {
            int   eidx  = i + half;
            float valid = (eidx < m) ? 1.0f : 0.0f;
            int   sn    = __shfl_sync(0xFFFFFFFFu, sn_l, eidx & 31);
            ulonglong2 el2 = ((const ulonglong2*)(g_hsrc + (size_t)sn * HD))[l16];

            u64t v01, v23, r01, r23, p01, p2;
            F2_ADD(v01, el2.x, er2.x);
            F2_ADD(v23, el2.y, er2.y);
            // lrelu = 0.6v + 0.4|v|
            F2_MUL(r01, v01, c06);
            F2_FMA(r01, v01 & amask, c04, r01);
            F2_MUL(r23, v23, c06);
            F2_FMA(r23, v23 & amask, c04, r23);
            // dot with attn
            F2_MUL(p01, r01, aw2.x);
            F2_FMA(p2, r23, aw2.y, p01);
            float plo, phi;
            F2_UNPACK(plo, phi, p2);
            float p = plo + phi;
            p += __shfl_xor_sync(0xFFFFFFFFu, p, 1);
            p += __shfl_xor_sync(0xFFFFFFFFu, p, 2);
            float a = __expf(p) * valid;
            u64t a2;
            F2_PACK1(a2, a);
            F2_FMA(acc01, el2.x, a2, acc01);
            F2_FMA(acc23, el2.y, a2, acc23);
            s += a;
        }
    }

    float ax, ay, az, aw_;
    F2_UNPACK(ax, ay, acc01);
    F2_UNPACK(az, aw_, acc23);

    ax += __shfl_xor_sync(0xFFFFFFFFu, ax, 16);
    ay += __shfl_xor_sync(0xFFFFFFFFu, ay, 16);
    az += __shfl_xor_sync(0xFFFFFFFFu, az, 16);
    aw_ += __shfl_xor_sync(0xFFFFFFFFu, aw_, 16);
    s  += __shfl_xor_sync(0xFFFFFFFFu, s, 16);

    if (lane == 0) g_deg[d] = 0;   // restore invariant for next graph replay

    if (half == 0) {
        float inv = (s > 0.f) ? (1.f / s) : 0.f;
        ((float4*)(out + (size_t)d * HD))[l16] =
            make_float4(ax * inv, ay * inv, az * inv, aw_ * inv);
    }
}

extern "C" void kernel_launch(void* const* d_in, const int* in_sizes, int n_in,
                              void* d_out, int out_size)
{
    const float* feat = (const float*)d_in[0];
    const int*   src  = (const int*)d_in[1];
    const int*   dst  = (const int*)d_in[2];
    const float* Wsrc = (const float*)d_in[3];
    const float* bsrc = (const float*)d_in[4];
    const float* Wdst = (const float*)d_in[5];
    const float* bdst = (const float*)d_in[6];
    const float* attn = (const float*)d_in[7];
    float* out = (float*)d_out;

    cudaFuncSetAttribute(proj_mma_kernel, cudaFuncAttributeMaxDynamicSharedMemorySize, SM_TOT);

    // Fork: padded-CSR scatter (src/dst only) || projection GEMM (feat/W only).
    cudaStream_t s2;
    cudaStreamCreateWithFlags(&s2, cudaStreamNonBlocking);
    cudaEvent_t evFork, evJoin;
    cudaEventCreateWithFlags(&evFork, cudaEventDisableTiming);
    cudaEventCreateWithFlags(&evJoin, cudaEventDisableTiming);

    cudaEventRecord(evFork, 0);
    cudaStreamWaitEvent(s2, evFork, 0);

    scatter_kernel<<<(N_EDGES / 4 + 255) / 256, 256, 0, s2>>>(src, dst);
    cudaEventRecord(evJoin, s2);

    proj_mma_kernel<<<(N_NODES + 127) / 128, 256, SM_TOT>>>(feat, Wsrc, bsrc, Wdst, bdst);

    cudaStreamWaitEvent(0, evJoin, 0);
    agg_kernel<<<(N_NODES * 32 + 255) / 256, 256>>>(out, attn);
}